// round 10
// baseline (speedup 1.0000x reference)
#include <cuda_runtime.h>

// EigVals: x (2, 9, 64, 192, 192) fp32 -> eigvalsh of symmetrized 3x3 per voxel,
// output (2*64*192*192, 3) fp32 ascending.

#define N_VOX   2359296            // 64*192*192
#define BATCH   2
#define TOTAL   (BATCH * N_VOX)    // 4718592 voxels
#define NGROUPS (TOTAL / 4)        // 1179648 float4 groups

// Compile-time lane select: guarantees ch[] stays in registers (no local-mem
// fallback from address-taken float4 indexing).
__device__ __forceinline__ float lane_of(const float4& v, int lane) {
    return (lane == 0) ? v.x : (lane == 1) ? v.y : (lane == 2) ? v.z : v.w;
}

// Fast acos on [-1,1]: Abramowitz-Stegun 4.4.45 (|err| <= 6.8e-5) with
// sqrt via one MUFU rsqrt. Branchless negative-range mirror.
__device__ __forceinline__ float fast_acosf(float r) {
    float t  = fabsf(r);
    float w  = 1.0f - t;                       // in [0, 1] since t <= 1
    float sr = (w > 1e-30f) ? w * rsqrtf(w) : 0.0f;   // sqrt(w)
    float poly = fmaf(t, fmaf(t, fmaf(t, -0.0187293f, 0.0742610f),
                              -0.2121144f), 1.5707288f);
    float a = sr * poly;                        // acos(|r|)
    return (r < 0.0f) ? (3.14159265358979f - a) : a;
}

__global__ __launch_bounds__(256)
void eigvals_kernel(const float* __restrict__ x, float* __restrict__ out)
{
    int g  = blockIdx.x * blockDim.x + threadIdx.x;  // group of 4 voxels
    if (g >= NGROUPS) return;
    int v0 = g * 4;

    // batch index: v0 in [0, 2*N_VOX). Groups never straddle batches (N_VOX % 4 == 0).
    int b = (v0 >= N_VOX) ? 1 : 0;
    // x[b, c, n] at offset b*9*N + c*N + n ; with v0 = b*N + n -> base = v0 + b*8*N
    const float* base = x + (size_t)v0 + (size_t)b * (8u * N_VOX);

    // 9 coalesced float4 channel loads (front-batched for MLP)
    float4 ch[9];
#pragma unroll
    for (int c = 0; c < 9; ++c)
        ch[c] = *reinterpret_cast<const float4*>(base + (size_t)c * N_VOX);

    float r12[12];  // 4 voxels x 3 ascending eigenvalues

#pragma unroll
    for (int lane = 0; lane < 4; ++lane) {
        // Symmetrize: A = 0.5*(M + M^T)  (channels: 0..8 row-major 3x3)
        float a00 = lane_of(ch[0], lane);
        float a11 = lane_of(ch[4], lane);
        float a22 = lane_of(ch[8], lane);
        float a01 = 0.5f * (lane_of(ch[1], lane) + lane_of(ch[3], lane));
        float a02 = 0.5f * (lane_of(ch[2], lane) + lane_of(ch[6], lane));
        float a12 = 0.5f * (lane_of(ch[5], lane) + lane_of(ch[7], lane));

        // Smith's trigonometric closed form for symmetric 3x3
        float q   = (a00 + a11 + a22) * (1.0f / 3.0f);
        float b00 = a00 - q, b11 = a11 - q, b22 = a22 - q;
        float p2  = b00 * b00 + b11 * b11 + b22 * b22
                  + 2.0f * (a01 * a01 + a02 * a02 + a12 * a12);

        // s = p2/6 ; p = sqrt(s) ; pinv = 1/p  — via ONE rsqrt (no div, no sqrt)
        float s    = p2 * (1.0f / 6.0f);
        bool  ok   = (p2 > 1e-30f);
        float pinv = ok ? rsqrtf(s) : 0.0f;
        float p    = s * pinv;               // s * s^-1/2 = sqrt(s); 0 when degenerate

        float c00 = b00 * pinv, c11 = b11 * pinv, c22 = b22 * pinv;
        float c01 = a01 * pinv, c02 = a02 * pinv, c12 = a12 * pinv;

        // det(B)/2, B = (A - qI)/p   (symmetric det)
        float detB = c00 * (c11 * c22 - c12 * c12)
                   - c01 * (c01 * c22 - c12 * c02)
                   + c02 * (c01 * c12 - c11 * c02);
        float r = 0.5f * detB;
        r = fminf(1.0f, fmaxf(-1.0f, r));

        float phi   = fast_acosf(r) * (1.0f / 3.0f);   // phi in [0, pi/3]
        float two_p = 2.0f * p;
        // cos(phi) in [0.5, 1]   -> largest
        // cos(phi + 2pi/3) in [-1, -0.5] -> smallest ; middle via trace identity
        float eL = q + two_p * __cosf(phi);
        float eS = q + two_p * __cosf(phi + 2.0943951023931953f);
        float eM = 3.0f * q - eL - eS;

        r12[lane * 3 + 0] = eS;
        r12[lane * 3 + 1] = eM;
        r12[lane * 3 + 2] = eL;
    }

    // 12 contiguous floats per thread -> 3x STG.128, every sector fully written
    float4* o = reinterpret_cast<float4*>(out + (size_t)v0 * 3);
    o[0] = make_float4(r12[0], r12[1], r12[2],  r12[3]);
    o[1] = make_float4(r12[4], r12[5], r12[6],  r12[7]);
    o[2] = make_float4(r12[8], r12[9], r12[10], r12[11]);
}

extern "C" void kernel_launch(void* const* d_in, const int* in_sizes, int n_in,
                              void* d_out, int out_size)
{
    const float* x = (const float*)d_in[0];
    float* out     = (float*)d_out;
    (void)in_sizes; (void)n_in; (void)out_size;

    const int threads = 256;
    const int blocks  = (NGROUPS + threads - 1) / threads;  // 4608
    eigvals_kernel<<<blocks, threads>>>(x, out);
}

// round 16
// speedup vs baseline: 1.0086x; 1.0086x over previous
#include <cuda_runtime.h>

// EigVals: x (2, 9, 64, 192, 192) fp32 -> eigvalsh of symmetrized 3x3 per voxel,
// output (2*64*192*192, 3) fp32 ascending.
// Persistent grid-stride kernel: one wave of 4 blocks/SM, streaming cache hints.

#define N_VOX   2359296            // 64*192*192
#define BATCH   2
#define TOTAL   (BATCH * N_VOX)    // 4718592 voxels
#define NGROUPS (TOTAL / 4)        // 1179648 float4 groups

#define NBLOCKS 608                // 152 SMs * 4 resident blocks (GB300)
#define NTHREADS 256

// Compile-time lane select: guarantees ch[] stays in registers.
__device__ __forceinline__ float lane_of(const float4& v, int lane) {
    return (lane == 0) ? v.x : (lane == 1) ? v.y : (lane == 2) ? v.z : v.w;
}

// Fast acos on [-1,1]: Abramowitz-Stegun 4.4.45 (|err| <= 6.8e-5).
// Branchless: w*rsqrt(max(w,eps)) == sqrt(w), exactly 0 at w=0.
__device__ __forceinline__ float fast_acosf(float r) {
    float t  = fabsf(r);
    float w  = fmaxf(1.0f - t, 0.0f);
    float sr = w * rsqrtf(fmaxf(w, 1e-38f));          // sqrt(w), 0 at w=0
    float poly = fmaf(t, fmaf(t, fmaf(t, -0.0187293f, 0.0742610f),
                              -0.2121144f), 1.5707288f);
    float a = sr * poly;                               // acos(|r|)
    return (r < 0.0f) ? (3.14159265358979f - a) : a;
}

__global__ __launch_bounds__(NTHREADS)
void eigvals_kernel(const float* __restrict__ x, float* __restrict__ out)
{
    const int stride = NBLOCKS * NTHREADS;             // 155648 threads
    for (int g = blockIdx.x * NTHREADS + threadIdx.x; g < NGROUPS; g += stride) {
        int v0 = g * 4;

        // batch index: groups never straddle batches (N_VOX % 4 == 0).
        int b = (v0 >= N_VOX) ? 1 : 0;
        // x[b, c, n] at offset b*9*N + c*N + n ; v0 = b*N + n -> base = v0 + b*8*N
        const float* base = x + (size_t)v0 + (size_t)b * (8u * N_VOX);

        // 9 coalesced float4 channel loads, streaming (zero reuse)
        float4 ch[9];
#pragma unroll
        for (int c = 0; c < 9; ++c)
            ch[c] = __ldcs(reinterpret_cast<const float4*>(base + (size_t)c * N_VOX));

        float r12[12];  // 4 voxels x 3 ascending eigenvalues

#pragma unroll
        for (int lane = 0; lane < 4; ++lane) {
            // Symmetrize: A = 0.5*(M + M^T)  (channels 0..8 row-major 3x3)
            float a00 = lane_of(ch[0], lane);
            float a11 = lane_of(ch[4], lane);
            float a22 = lane_of(ch[8], lane);
            float a01 = 0.5f * (lane_of(ch[1], lane) + lane_of(ch[3], lane));
            float a02 = 0.5f * (lane_of(ch[2], lane) + lane_of(ch[6], lane));
            float a12 = 0.5f * (lane_of(ch[5], lane) + lane_of(ch[7], lane));

            // Smith's trigonometric closed form for symmetric 3x3
            float q   = (a00 + a11 + a22) * (1.0f / 3.0f);
            float b00 = a00 - q, b11 = a11 - q, b22 = a22 - q;
            float p2  = b00 * b00 + b11 * b11 + b22 * b22
                      + 2.0f * (a01 * a01 + a02 * a02 + a12 * a12);

            // s = p2/6 ; pinv = 1/sqrt(s) ; p = sqrt(s) — branchless, NaN-safe:
            // s == 0 => all deviatoric terms are exactly 0 => c** = 0, p = 0.
            float s    = p2 * (1.0f / 6.0f);
            float pinv = rsqrtf(fmaxf(s, 1e-38f));
            float p    = s * pinv;

            float c00 = b00 * pinv, c11 = b11 * pinv, c22 = b22 * pinv;
            float c01 = a01 * pinv, c02 = a02 * pinv, c12 = a12 * pinv;

            // det(B)/2, B = (A - qI)/p   (symmetric det)
            float detB = c00 * (c11 * c22 - c12 * c12)
                       - c01 * (c01 * c22 - c12 * c02)
                       + c02 * (c01 * c12 - c11 * c02);
            float r = 0.5f * detB;
            r = fminf(1.0f, fmaxf(-1.0f, r));

            float phi   = fast_acosf(r) * (1.0f / 3.0f);   // phi in [0, pi/3]
            float two_p = 2.0f * p;
            // cos(phi) in [0.5,1] -> largest ; cos(phi+2pi/3) in [-1,-0.5] -> smallest
            float eL = q + two_p * __cosf(phi);
            float eS = q + two_p * __cosf(phi + 2.0943951023931953f);
            float eM = 3.0f * q - eL - eS;

            r12[lane * 3 + 0] = eS;
            r12[lane * 3 + 1] = eM;
            r12[lane * 3 + 2] = eL;
        }

        // 12 contiguous floats per thread -> 3x STG.128 streaming
        float4* o = reinterpret_cast<float4*>(out + (size_t)v0 * 3);
        __stcs(o + 0, make_float4(r12[0], r12[1], r12[2],  r12[3]));
        __stcs(o + 1, make_float4(r12[4], r12[5], r12[6],  r12[7]));
        __stcs(o + 2, make_float4(r12[8], r12[9], r12[10], r12[11]));
    }
}

extern "C" void kernel_launch(void* const* d_in, const int* in_sizes, int n_in,
                              void* d_out, int out_size)
{
    const float* x = (const float*)d_in[0];
    float* out     = (float*)d_out;
    (void)in_sizes; (void)n_in; (void)out_size;

    eigvals_kernel<<<NBLOCKS, NTHREADS>>>(x, out);
}